// round 5
// baseline (speedup 1.0000x reference)
#include <cuda_runtime.h>
#include <cuda_fp16.h>

#define NMAX   100000
#define EMAX   1600000
#define NGRAPH 64
#define NFEAT  128
#define NHID   64
#define NCLASS 10
#define SCAN_B 512

// ---- scratch (allocation-free rule: __device__ globals) ----
__device__ int   g_src[EMAX];
__device__ int   g_dst[EMAX];
__device__ int   g_csrc[EMAX];          // CSR: src ids grouped by dst
__device__ int   g_ecnt[NMAX];          // in-degree (edges only)
__device__ int   g_off[NMAX];           // CSR row offsets (exclusive scan)
__device__ int   g_cursor[NMAX];
__device__ int   g_scan[NMAX];
__device__ int   g_bsum[256];
__device__ int   g_boff[256];
__device__ float g_dinv[NMAX];
__device__ alignas(16) __half g_hs16[(size_t)NMAX * NHID];   // fp16 hs for gather
__device__ alignas(16) float  g_accA[(size_t)NMAX * NHID];
__device__ alignas(16) float  g_accB[(size_t)NMAX * NHID];
__device__ float g_gsum[NGRAPH * NHID];
__device__ int   g_gcnt[NGRAPH];

// ---- f32x2 packed-math helpers (sm_100+: FFMA2 only via PTX) --------------
__device__ __forceinline__ unsigned long long ffma2(unsigned long long a,
                                                    unsigned long long b,
                                                    unsigned long long c) {
    unsigned long long d;
    asm("fma.rn.f32x2 %0, %1, %2, %3;" : "=l"(d) : "l"(a), "l"(b), "l"(c));
    return d;
}
__device__ __forceinline__ unsigned long long bcast2(float x) {
    unsigned long long d;
    asm("mov.b64 %0, {%1, %1};" : "=l"(d) : "f"(x));
    return d;
}
__device__ __forceinline__ void unpack2(unsigned long long p, float& lo, float& hi) {
    asm("mov.b64 {%0, %1}, %2;" : "=f"(lo), "=f"(hi) : "l"(p));
}
union F4U2 { float4 f; unsigned long long u[2]; };
union H8I4 { int4 i; __half2 h[4]; };

// ---------------------------------------------------------------------------
__global__ void k_init(int N) {
    int i = blockIdx.x * blockDim.x + threadIdx.x;
    if (i < N) g_ecnt[i] = 0;
    if (i < NGRAPH * NHID) g_gsum[i] = 0.f;
    if (i < NGRAPH) g_gcnt[i] = 0;
}

__global__ void k_edge_prep(const int* __restrict__ ei, int E, int N) {
    int e = blockIdx.x * blockDim.x + threadIdx.x;
    if (e >= E) return;
    int s = ei[e];
    int d = ei[E + e];
    if ((unsigned)s >= (unsigned)N || (unsigned)d >= (unsigned)N) {
        g_src[e] = -1; g_dst[e] = -1; return;
    }
    g_src[e] = s;
    g_dst[e] = d;
    atomicAdd(&g_ecnt[d], 1);
}

// ---- 3-kernel exclusive scan of g_ecnt -> g_off -------------------------
__device__ __forceinline__ int block_incl_scan(int v, int tid) {
    __shared__ int wsum[16];
    int lane = tid & 31, w = tid >> 5;
    int x = v;
#pragma unroll
    for (int o = 1; o < 32; o <<= 1) {
        int t = __shfl_up_sync(0xffffffffu, x, o);
        if (lane >= o) x += t;
    }
    if (lane == 31) wsum[w] = x;
    __syncthreads();
    if (w == 0) {
        int y = (lane < (blockDim.x >> 5)) ? wsum[lane] : 0;
#pragma unroll
        for (int o = 1; o < 16; o <<= 1) {
            int t = __shfl_up_sync(0xffffffffu, y, o);
            if (lane >= o) y += t;
        }
        if (lane < 16) wsum[lane] = y;
    }
    __syncthreads();
    return x + (w > 0 ? wsum[w - 1] : 0);
}

__global__ void k_scanA(int N) {
    int i = blockIdx.x * SCAN_B + threadIdx.x;
    int v = (i < N) ? g_ecnt[i] : 0;
    int incl = block_incl_scan(v, threadIdx.x);
    if (i < N) g_scan[i] = incl - v;
    if (threadIdx.x == SCAN_B - 1) g_bsum[blockIdx.x] = incl;
}

__global__ void k_scanB(int nb) {
    int t = threadIdx.x;
    int v = (t < nb) ? g_bsum[t] : 0;
    int incl = block_incl_scan(v, t);
    if (t < 256) g_boff[t] = incl - v;
}

__global__ void k_scanC(int N) {
    int i = blockIdx.x * SCAN_B + threadIdx.x;
    if (i >= N) return;
    int off = g_scan[i] + g_boff[blockIdx.x];
    g_off[i] = off;
    g_cursor[i] = off;
    g_dinv[i] = rsqrtf((float)(g_ecnt[i] + 1));   // +1 self-loop
}

__global__ void k_csr_fill(int E) {
    int e = blockIdx.x * blockDim.x + threadIdx.x;
    if (e >= E) return;
    int s = g_src[e];
    if (s < 0) return;
    int d = g_dst[e];
    int pos = atomicAdd(&g_cursor[d], 1);
    g_csrc[pos] = s;
}

// ---------------------------------------------------------------------------
// Shared GEMM epilogue: scale by dinv, convert to fp16, store 8 cols (16B).
__device__ __forceinline__ void store_hs16(int n, int cg8, float dv,
                                           const unsigned long long* a /*4 pairs*/) {
    H8I4 o;
#pragma unroll
    for (int p = 0; p < 4; p++) {
        float lo, hi;
        unpack2(a[p], lo, hi);
        o.h[p] = __floats2half2_rn(lo * dv, hi * dv);
    }
    reinterpret_cast<int4*>(g_hs16)[(size_t)n * 8 + cg8] = o.i;
}

// Layer 1 GEMM: hs16[n] = fp16(dinv[n] * (x[n] @ W1)).
// 128 threads: cg8 = tid&7 -> 8 cols, ng = tid>>3 -> 2 nodes. 32 nodes/block.
__global__ void k_gemm1(const float* __restrict__ x, const float* __restrict__ W, int N) {
    __shared__ float4 Wsh[NFEAT * 16];   // [k][c4]  32KB
    __shared__ float4 xsh[32 * 32];      // [node][k4] 16KB
    int tid = threadIdx.x;
    const float4* W4 = reinterpret_cast<const float4*>(W);
    const float4* x4 = reinterpret_cast<const float4*>(x);
#pragma unroll
    for (int i = tid; i < NFEAT * 16; i += 128) Wsh[i] = W4[i];
    int nb = blockIdx.x * 32;
#pragma unroll
    for (int i = tid; i < 32 * 32; i += 128) {
        int n = nb + (i >> 5);
        xsh[i] = (n < N) ? x4[(size_t)n * 32 + (i & 31)]
                         : make_float4(0.f, 0.f, 0.f, 0.f);
    }
    __syncthreads();

    int cg8 = tid & 7;        // 8 cols: cg8*8 .. +7  (4 f32x2 pairs)
    int ng  = tid >> 3;       // 2 nodes: ng*2, ng*2+1
    unsigned long long a0[4] = {0ull, 0ull, 0ull, 0ull};
    unsigned long long a1[4] = {0ull, 0ull, 0ull, 0ull};

#pragma unroll 4
    for (int k4 = 0; k4 < 32; k4++) {
        float4 xv0 = xsh[(ng * 2 + 0) * 32 + k4];
        float4 xv1 = xsh[(ng * 2 + 1) * 32 + k4];
#pragma unroll
        for (int kk = 0; kk < 4; kk++) {
            F4U2 wA, wB;
            wA.f = Wsh[(4 * k4 + kk) * 16 + cg8 * 2];
            wB.f = Wsh[(4 * k4 + kk) * 16 + cg8 * 2 + 1];
            float xs0 = (kk == 0) ? xv0.x : (kk == 1) ? xv0.y : (kk == 2) ? xv0.z : xv0.w;
            float xs1 = (kk == 0) ? xv1.x : (kk == 1) ? xv1.y : (kk == 2) ? xv1.z : xv1.w;
            unsigned long long p0 = bcast2(xs0);
            unsigned long long p1 = bcast2(xs1);
            a0[0] = ffma2(p0, wA.u[0], a0[0]); a0[1] = ffma2(p0, wA.u[1], a0[1]);
            a0[2] = ffma2(p0, wB.u[0], a0[2]); a0[3] = ffma2(p0, wB.u[1], a0[3]);
            a1[0] = ffma2(p1, wA.u[0], a1[0]); a1[1] = ffma2(p1, wA.u[1], a1[1]);
            a1[2] = ffma2(p1, wB.u[0], a1[2]); a1[3] = ffma2(p1, wB.u[1], a1[3]);
        }
    }
    int n0 = nb + ng * 2;
    if (n0     < N) store_hs16(n0,     cg8, g_dinv[n0],     a0);
    if (n0 + 1 < N) store_hs16(n0 + 1, cg8, g_dinv[n0 + 1], a1);
}

// Layers 2/3: in = relu(dinv*accPrev + bPrev); hs16 = fp16(dinv * (in @ W)).
__global__ void k_gemm23(const float* __restrict__ accPrev, const float* __restrict__ bPrev,
                         const float* __restrict__ W, int N) {
    __shared__ float4 Wsh[NHID * 16];    // 16KB
    __shared__ float4 xsh[32 * 16];      // 8KB
    int tid = threadIdx.x;
    const float4* W4 = reinterpret_cast<const float4*>(W);
    const float4* acc4 = reinterpret_cast<const float4*>(accPrev);
    const float4* b4p = reinterpret_cast<const float4*>(bPrev);
#pragma unroll
    for (int i = tid; i < NHID * 16; i += 128) Wsh[i] = W4[i];
    int nb = blockIdx.x * 32;
#pragma unroll
    for (int i = tid; i < 32 * 16; i += 128) {
        int n = nb + (i >> 4);
        int k4 = i & 15;
        float4 o = make_float4(0.f, 0.f, 0.f, 0.f);
        if (n < N) {
            float4 av = acc4[(size_t)n * 16 + k4];
            float4 bb = b4p[k4];
            float dv = g_dinv[n];
            o.x = fmaxf(fmaf(dv, av.x, bb.x), 0.f);
            o.y = fmaxf(fmaf(dv, av.y, bb.y), 0.f);
            o.z = fmaxf(fmaf(dv, av.z, bb.z), 0.f);
            o.w = fmaxf(fmaf(dv, av.w, bb.w), 0.f);
        }
        xsh[i] = o;
    }
    __syncthreads();

    int cg8 = tid & 7;
    int ng  = tid >> 3;
    unsigned long long a0[4] = {0ull, 0ull, 0ull, 0ull};
    unsigned long long a1[4] = {0ull, 0ull, 0ull, 0ull};

#pragma unroll 4
    for (int k4 = 0; k4 < 16; k4++) {
        float4 xv0 = xsh[(ng * 2 + 0) * 16 + k4];
        float4 xv1 = xsh[(ng * 2 + 1) * 16 + k4];
#pragma unroll
        for (int kk = 0; kk < 4; kk++) {
            F4U2 wA, wB;
            wA.f = Wsh[(4 * k4 + kk) * 16 + cg8 * 2];
            wB.f = Wsh[(4 * k4 + kk) * 16 + cg8 * 2 + 1];
            float xs0 = (kk == 0) ? xv0.x : (kk == 1) ? xv0.y : (kk == 2) ? xv0.z : xv0.w;
            float xs1 = (kk == 0) ? xv1.x : (kk == 1) ? xv1.y : (kk == 2) ? xv1.z : xv1.w;
            unsigned long long p0 = bcast2(xs0);
            unsigned long long p1 = bcast2(xs1);
            a0[0] = ffma2(p0, wA.u[0], a0[0]); a0[1] = ffma2(p0, wA.u[1], a0[1]);
            a0[2] = ffma2(p0, wB.u[0], a0[2]); a0[3] = ffma2(p0, wB.u[1], a0[3]);
            a1[0] = ffma2(p1, wA.u[0], a1[0]); a1[1] = ffma2(p1, wA.u[1], a1[1]);
            a1[2] = ffma2(p1, wB.u[0], a1[2]); a1[3] = ffma2(p1, wB.u[1], a1[3]);
        }
    }
    int n0 = nb + ng * 2;
    if (n0     < N) store_hs16(n0,     cg8, g_dinv[n0],     a0);
    if (n0 + 1 < N) store_hs16(n0 + 1, cg8, g_dinv[n0 + 1], a1);
}

// ---------------------------------------------------------------------------
// CSR gather aggregation (fp16 source, fp32 accumulate):
// acc[n] = hs[n] (self-loop) + sum_{s in in(n)} hs[s].
// One warp per node; 8 lanes x 16B (8 halves) cover the 128B row; 4 edges in flight.
__global__ void k_agg(float* __restrict__ accOut, int N) {
    int warp = (blockIdx.x * blockDim.x + threadIdx.x) >> 5;
    if (warp >= N) return;
    int lane = threadIdx.x & 31;
    int p = lane & 7;        // 16B chunk (cols p*8 .. p*8+7)
    int q = lane >> 3;       // edge slot 0..3
    const int4* h16 = reinterpret_cast<const int4*>(g_hs16);
    int n = warp;
    int start = g_off[n];
    int len = g_ecnt[n];

    float a[8];
    if (q == 0) {            // self-loop init
        H8I4 v; v.i = h16[(size_t)n * 8 + p];
#pragma unroll
        for (int i = 0; i < 4; i++) {
            float2 f = __half22float2(v.h[i]);
            a[2 * i] = f.x; a[2 * i + 1] = f.y;
        }
    } else {
#pragma unroll
        for (int i = 0; i < 8; i++) a[i] = 0.f;
    }
    for (int j = start + q; j < start + len; j += 4) {
        int s = g_csrc[j];
        H8I4 v; v.i = h16[(size_t)s * 8 + p];
#pragma unroll
        for (int i = 0; i < 4; i++) {
            float2 f = __half22float2(v.h[i]);
            a[2 * i] += f.x; a[2 * i + 1] += f.y;
        }
    }
    const unsigned F = 0xffffffffu;
#pragma unroll
    for (int off = 8; off <= 16; off <<= 1) {
#pragma unroll
        for (int i = 0; i < 8; i++) a[i] += __shfl_xor_sync(F, a[i], off);
    }
    if (lane < 8) {
        float4* out4 = reinterpret_cast<float4*>(accOut);
        out4[(size_t)n * 16 + lane * 2]     = make_float4(a[0], a[1], a[2], a[3]);
        out4[(size_t)n * 16 + lane * 2 + 1] = make_float4(a[4], a[5], a[6], a[7]);
    }
}

// ---------------------------------------------------------------------------
// Pool: per-graph sum of relu(dinv*acc3 + b3) with 4-node run-length batching.
__global__ void k_pool(const float* __restrict__ acc3, const float* __restrict__ b3,
                       const int* __restrict__ batch, int N) {
    int t = blockIdx.x * blockDim.x + threadIdx.x;
    int c = t & 63;
    int n0 = (t >> 6) * 4;
    if (n0 >= N) return;
    float b = b3[c];
    float accum = 0.f;
    int cnt = 0;
    int gprev = -1;
    for (int j = 0; j < 4; j++) {
        int n = n0 + j;
        if (n >= N) break;
        int g = batch[n];
        if ((unsigned)g >= NGRAPH) continue;
        if (g != gprev) {
            if (gprev >= 0) {
                atomicAdd(&g_gsum[gprev * NHID + c], accum);
                if (c == 0) atomicAdd(&g_gcnt[gprev], cnt);
            }
            accum = 0.f; cnt = 0; gprev = g;
        }
        accum += fmaxf(fmaf(g_dinv[n], acc3[(size_t)n * NHID + c], b), 0.f);
        cnt++;
    }
    if (gprev >= 0) {
        atomicAdd(&g_gsum[gprev * NHID + c], accum);
        if (c == 0) atomicAdd(&g_gcnt[gprev], cnt);
    }
}

__global__ void k_head(const float* __restrict__ Wl, const float* __restrict__ bl,
                       float* __restrict__ out) {
    int g = threadIdx.x;
    if (g >= NGRAPH) return;
    float cnt = fmaxf((float)g_gcnt[g], 1.f);
    float inv = 1.f / cnt;
    float l[NCLASS];
#pragma unroll
    for (int c = 0; c < NCLASS; c++) l[c] = bl[c];
    for (int k = 0; k < NHID; k++) {
        float p = g_gsum[g * NHID + k] * inv;
#pragma unroll
        for (int c = 0; c < NCLASS; c++) l[c] = fmaf(p, Wl[k * NCLASS + c], l[c]);
    }
    float m = l[0];
#pragma unroll
    for (int c = 1; c < NCLASS; c++) m = fmaxf(m, l[c]);
    float s = 0.f;
#pragma unroll
    for (int c = 0; c < NCLASS; c++) { l[c] = __expf(l[c] - m); s += l[c]; }
    float is = 1.f / s;
#pragma unroll
    for (int c = 0; c < NCLASS; c++) out[g * NCLASS + c] = l[c] * is;
}

// ---------------------------------------------------------------------------
extern "C" void kernel_launch(void* const* d_in, const int* in_sizes, int n_in,
                              void* d_out, int out_size) {
    const float* x     = (const float*)d_in[0];
    const int*   ei    = (const int*)d_in[1];
    const int*   batch = (const int*)d_in[2];
    const float* W1 = (const float*)d_in[3];
    const float* b1 = (const float*)d_in[4];
    const float* W2 = (const float*)d_in[5];
    const float* b2 = (const float*)d_in[6];
    const float* W3 = (const float*)d_in[7];
    const float* b3 = (const float*)d_in[8];
    const float* Wl = (const float*)d_in[9];
    const float* bl = (const float*)d_in[10];
    float* out = (float*)d_out;

    int N = in_sizes[0] / NFEAT;
    int E = in_sizes[1] / 2;

    float *accA = nullptr, *accB = nullptr;
    cudaGetSymbolAddress((void**)&accA, g_accA);
    cudaGetSymbolAddress((void**)&accB, g_accB);

    const int T = 256;
    int nScanBlocks = (N + SCAN_B - 1) / SCAN_B;

    k_init<<<(N + T - 1) / T, T>>>(N);
    k_edge_prep<<<(E + T - 1) / T, T>>>(ei, E, N);
    k_scanA<<<nScanBlocks, SCAN_B>>>(N);
    k_scanB<<<1, 256>>>(nScanBlocks);
    k_scanC<<<nScanBlocks, SCAN_B>>>(N);
    k_csr_fill<<<(E + T - 1) / T, T>>>(E);

    int gemmBlocks = (N + 31) / 32;
    int aggBlocks = (N * 32 + T - 1) / T;

    // Layer 1
    k_gemm1<<<gemmBlocks, 128>>>(x, W1, N);
    k_agg<<<aggBlocks, T>>>(accA, N);
    // Layer 2
    k_gemm23<<<gemmBlocks, 128>>>(accA, b1, W2, N);
    k_agg<<<aggBlocks, T>>>(accB, N);
    // Layer 3
    k_gemm23<<<gemmBlocks, 128>>>(accB, b2, W3, N);
    k_agg<<<aggBlocks, T>>>(accA, N);

    // Pool + head
    k_pool<<<(((N + 3) / 4) * 64 + T - 1) / T, T>>>(accA, b3, batch, N);
    k_head<<<1, 64>>>(Wl, bl, out);
}

// round 7
// speedup vs baseline: 1.2573x; 1.2573x over previous
#include <cuda_runtime.h>

#define NMAX   100000
#define EMAX   1600000
#define NGRAPH 64
#define NFEAT  128
#define NHID   64
#define NCLASS 10
#define SCAN_B 512

// ---- scratch (allocation-free rule: __device__ globals) ----
__device__ int   g_csrc[EMAX];          // CSR: src ids grouped by dst
__device__ int   g_ecnt[NMAX];          // in-degree (edges only)
__device__ int   g_off[NMAX];           // CSR row offsets (exclusive scan)
__device__ int   g_cursor[NMAX];
__device__ int   g_scan[NMAX];
__device__ int   g_bsum[256];
__device__ int   g_boff[256];
__device__ float g_dinv[NMAX];
__device__ alignas(16) float g_hs  [(size_t)NMAX * NHID];
__device__ alignas(16) float g_accA[(size_t)NMAX * NHID];
__device__ alignas(16) float g_accB[(size_t)NMAX * NHID];
__device__ float g_gsum[NGRAPH * NHID];
__device__ int   g_gcnt[NGRAPH];

// ---------------------------------------------------------------------------
__global__ void k_init(int N) {
    int i = blockIdx.x * blockDim.x + threadIdx.x;
    if (i < N) g_ecnt[i] = 0;
    if (i < NGRAPH * NHID) g_gsum[i] = 0.f;
    if (i < NGRAPH) g_gcnt[i] = 0;
}

// histogram in-degree straight from ei (no staging arrays)
__global__ void k_edge_prep(const int* __restrict__ ei, int E, int N) {
    int e = blockIdx.x * blockDim.x + threadIdx.x;
    if (e >= E) return;
    int s = ei[e];
    int d = ei[E + e];
    if ((unsigned)s >= (unsigned)N || (unsigned)d >= (unsigned)N) return;
    atomicAdd(&g_ecnt[d], 1);
}

// ---- 3-kernel exclusive scan of g_ecnt -> g_off -------------------------
__device__ __forceinline__ int block_incl_scan(int v, int tid) {
    __shared__ int wsum[16];
    int lane = tid & 31, w = tid >> 5;
    int x = v;
#pragma unroll
    for (int o = 1; o < 32; o <<= 1) {
        int t = __shfl_up_sync(0xffffffffu, x, o);
        if (lane >= o) x += t;
    }
    if (lane == 31) wsum[w] = x;
    __syncthreads();
    if (w == 0) {
        int y = (lane < (blockDim.x >> 5)) ? wsum[lane] : 0;
#pragma unroll
        for (int o = 1; o < 16; o <<= 1) {
            int t = __shfl_up_sync(0xffffffffu, y, o);
            if (lane >= o) y += t;
        }
        if (lane < 16) wsum[lane] = y;
    }
    __syncthreads();
    return x + (w > 0 ? wsum[w - 1] : 0);
}

__global__ void k_scanA(int N) {
    int i = blockIdx.x * SCAN_B + threadIdx.x;
    int v = (i < N) ? g_ecnt[i] : 0;
    int incl = block_incl_scan(v, threadIdx.x);
    if (i < N) g_scan[i] = incl - v;
    if (threadIdx.x == SCAN_B - 1) g_bsum[blockIdx.x] = incl;
}

__global__ void k_scanB(int nb) {
    int t = threadIdx.x;
    int v = (t < nb) ? g_bsum[t] : 0;
    int incl = block_incl_scan(v, t);
    if (t < 256) g_boff[t] = incl - v;
}

__global__ void k_scanC(int N) {
    int i = blockIdx.x * SCAN_B + threadIdx.x;
    if (i >= N) return;
    int off = g_scan[i] + g_boff[blockIdx.x];
    g_off[i] = off;
    g_cursor[i] = off;
    g_dinv[i] = rsqrtf((float)(g_ecnt[i] + 1));   // +1 self-loop
}

__global__ void k_csr_fill(const int* __restrict__ ei, int E, int N) {
    int e = blockIdx.x * blockDim.x + threadIdx.x;
    if (e >= E) return;
    int s = ei[e];
    int d = ei[E + e];
    if ((unsigned)s >= (unsigned)N || (unsigned)d >= (unsigned)N) return;
    int pos = atomicAdd(&g_cursor[d], 1);
    g_csrc[pos] = s;
}

// ---------------------------------------------------------------------------
// Layer 1 GEMM: hs[n] = dinv[n] * (x[n] @ W1).
// 128 threads, 32 nodes/block; each thread: 4 nodes x 4 cols, k blocked by 4.
__global__ void k_gemm1(const float* __restrict__ x, const float* __restrict__ W, int N) {
    __shared__ float4 Wsh[NFEAT * 16];   // [k][c4]  32KB
    __shared__ float4 xsh[32 * 32];      // [node][k4] 16KB
    int tid = threadIdx.x;
    const float4* W4 = reinterpret_cast<const float4*>(W);
    const float4* x4 = reinterpret_cast<const float4*>(x);
#pragma unroll
    for (int i = tid; i < NFEAT * 16; i += 128) Wsh[i] = W4[i];
    int nb = blockIdx.x * 32;
#pragma unroll
    for (int i = tid; i < 32 * 32; i += 128) {
        int n = nb + (i >> 5);
        xsh[i] = (n < N) ? x4[(size_t)n * 32 + (i & 31)]
                         : make_float4(0.f, 0.f, 0.f, 0.f);
    }
    __syncthreads();

    int cg = tid & 15;        // col group: cols cg*4..cg*4+3
    int ng = tid >> 4;        // node group: nodes ng*4..ng*4+3
    float4 a[4];
#pragma unroll
    for (int j = 0; j < 4; j++) a[j] = make_float4(0.f, 0.f, 0.f, 0.f);

#pragma unroll 4
    for (int k4 = 0; k4 < 32; k4++) {
        float4 w0 = Wsh[(4 * k4 + 0) * 16 + cg];
        float4 w1 = Wsh[(4 * k4 + 1) * 16 + cg];
        float4 w2 = Wsh[(4 * k4 + 2) * 16 + cg];
        float4 w3 = Wsh[(4 * k4 + 3) * 16 + cg];
#pragma unroll
        for (int j = 0; j < 4; j++) {
            float4 xv = xsh[(ng * 4 + j) * 32 + k4];
            a[j].x = fmaf(xv.x, w0.x, a[j].x); a[j].y = fmaf(xv.x, w0.y, a[j].y);
            a[j].z = fmaf(xv.x, w0.z, a[j].z); a[j].w = fmaf(xv.x, w0.w, a[j].w);
            a[j].x = fmaf(xv.y, w1.x, a[j].x); a[j].y = fmaf(xv.y, w1.y, a[j].y);
            a[j].z = fmaf(xv.y, w1.z, a[j].z); a[j].w = fmaf(xv.y, w1.w, a[j].w);
            a[j].x = fmaf(xv.z, w2.x, a[j].x); a[j].y = fmaf(xv.z, w2.y, a[j].y);
            a[j].z = fmaf(xv.z, w2.z, a[j].z); a[j].w = fmaf(xv.z, w2.w, a[j].w);
            a[j].x = fmaf(xv.w, w3.x, a[j].x); a[j].y = fmaf(xv.w, w3.y, a[j].y);
            a[j].z = fmaf(xv.w, w3.z, a[j].z); a[j].w = fmaf(xv.w, w3.w, a[j].w);
        }
    }
    float4* hs4 = reinterpret_cast<float4*>(g_hs);
#pragma unroll
    for (int j = 0; j < 4; j++) {
        int n = nb + ng * 4 + j;
        if (n < N) {
            float v = g_dinv[n];
            float4 o = a[j];
            o.x *= v; o.y *= v; o.z *= v; o.w *= v;
            hs4[(size_t)n * 16 + cg] = o;
        }
    }
}

// Layers 2/3 GEMM: in = relu(dinv*accPrev + bPrev); hs = dinv * (in @ W).
__global__ void k_gemm23(const float* __restrict__ accPrev, const float* __restrict__ bPrev,
                         const float* __restrict__ W, int N) {
    __shared__ float4 Wsh[NHID * 16];    // 16KB
    __shared__ float4 xsh[32 * 16];      // 8KB
    int tid = threadIdx.x;
    const float4* W4 = reinterpret_cast<const float4*>(W);
    const float4* acc4 = reinterpret_cast<const float4*>(accPrev);
    const float4* b4p = reinterpret_cast<const float4*>(bPrev);
#pragma unroll
    for (int i = tid; i < NHID * 16; i += 128) Wsh[i] = W4[i];
    int nb = blockIdx.x * 32;
#pragma unroll
    for (int i = tid; i < 32 * 16; i += 128) {
        int n = nb + (i >> 4);
        int k4 = i & 15;
        float4 o = make_float4(0.f, 0.f, 0.f, 0.f);
        if (n < N) {
            float4 av = acc4[(size_t)n * 16 + k4];
            float4 bb = b4p[k4];
            float dv = g_dinv[n];
            o.x = fmaxf(fmaf(dv, av.x, bb.x), 0.f);
            o.y = fmaxf(fmaf(dv, av.y, bb.y), 0.f);
            o.z = fmaxf(fmaf(dv, av.z, bb.z), 0.f);
            o.w = fmaxf(fmaf(dv, av.w, bb.w), 0.f);
        }
        xsh[i] = o;
    }
    __syncthreads();

    int cg = tid & 15;
    int ng = tid >> 4;
    float4 a[4];
#pragma unroll
    for (int j = 0; j < 4; j++) a[j] = make_float4(0.f, 0.f, 0.f, 0.f);

#pragma unroll 4
    for (int k4 = 0; k4 < 16; k4++) {
        float4 w0 = Wsh[(4 * k4 + 0) * 16 + cg];
        float4 w1 = Wsh[(4 * k4 + 1) * 16 + cg];
        float4 w2 = Wsh[(4 * k4 + 2) * 16 + cg];
        float4 w3 = Wsh[(4 * k4 + 3) * 16 + cg];
#pragma unroll
        for (int j = 0; j < 4; j++) {
            float4 xv = xsh[(ng * 4 + j) * 16 + k4];
            a[j].x = fmaf(xv.x, w0.x, a[j].x); a[j].y = fmaf(xv.x, w0.y, a[j].y);
            a[j].z = fmaf(xv.x, w0.z, a[j].z); a[j].w = fmaf(xv.x, w0.w, a[j].w);
            a[j].x = fmaf(xv.y, w1.x, a[j].x); a[j].y = fmaf(xv.y, w1.y, a[j].y);
            a[j].z = fmaf(xv.y, w1.z, a[j].z); a[j].w = fmaf(xv.y, w1.w, a[j].w);
            a[j].x = fmaf(xv.z, w2.x, a[j].x); a[j].y = fmaf(xv.z, w2.y, a[j].y);
            a[j].z = fmaf(xv.z, w2.z, a[j].z); a[j].w = fmaf(xv.z, w2.w, a[j].w);
            a[j].x = fmaf(xv.w, w3.x, a[j].x); a[j].y = fmaf(xv.w, w3.y, a[j].y);
            a[j].z = fmaf(xv.w, w3.z, a[j].z); a[j].w = fmaf(xv.w, w3.w, a[j].w);
        }
    }
    float4* hs4 = reinterpret_cast<float4*>(g_hs);
#pragma unroll
    for (int j = 0; j < 4; j++) {
        int n = nb + ng * 4 + j;
        if (n < N) {
            float v = g_dinv[n];
            float4 o = a[j];
            o.x *= v; o.y *= v; o.z *= v; o.w *= v;
            hs4[(size_t)n * 16 + cg] = o;
        }
    }
}

// ---------------------------------------------------------------------------
// CSR gather aggregation: acc[n] = hs[n] (self-loop) + sum_{s in in(n)} hs[s].
// One warp per node; 4 edge slots (q=lane>>3), 8 lanes x 32B cover the row.
// Edge loop unrolled x2 for MLP against L2 latency.
__global__ void k_agg(float* __restrict__ accOut, int N) {
    int warp = (blockIdx.x * blockDim.x + threadIdx.x) >> 5;
    if (warp >= N) return;
    int lane = threadIdx.x & 31;
    int p = lane & 7;        // col chunk: float4s p*2, p*2+1
    int q = lane >> 3;       // edge slot 0..3
    const float4* hs4 = reinterpret_cast<const float4*>(g_hs);
    const int* __restrict__ csrc = g_csrc;
    int n = warp;
    int start = g_off[n];
    int end = start + g_ecnt[n];

    float4 a0, a1;
    if (q == 0) {            // self-loop init
        a0 = hs4[(size_t)n * 16 + p * 2];
        a1 = hs4[(size_t)n * 16 + p * 2 + 1];
    } else {
        a0 = make_float4(0.f, 0.f, 0.f, 0.f);
        a1 = make_float4(0.f, 0.f, 0.f, 0.f);
    }
    int j = start + q;
    for (; j + 4 < end; j += 8) {
        int sA = csrc[j];
        int sB = csrc[j + 4];
        float4 vA0 = hs4[(size_t)sA * 16 + p * 2];
        float4 vA1 = hs4[(size_t)sA * 16 + p * 2 + 1];
        float4 vB0 = hs4[(size_t)sB * 16 + p * 2];
        float4 vB1 = hs4[(size_t)sB * 16 + p * 2 + 1];
        a0.x += vA0.x; a0.y += vA0.y; a0.z += vA0.z; a0.w += vA0.w;
        a1.x += vA1.x; a1.y += vA1.y; a1.z += vA1.z; a1.w += vA1.w;
        a0.x += vB0.x; a0.y += vB0.y; a0.z += vB0.z; a0.w += vB0.w;
        a1.x += vB1.x; a1.y += vB1.y; a1.z += vB1.z; a1.w += vB1.w;
    }
    if (j < end) {
        int s = csrc[j];
        float4 v0 = hs4[(size_t)s * 16 + p * 2];
        float4 v1 = hs4[(size_t)s * 16 + p * 2 + 1];
        a0.x += v0.x; a0.y += v0.y; a0.z += v0.z; a0.w += v0.w;
        a1.x += v1.x; a1.y += v1.y; a1.z += v1.z; a1.w += v1.w;
    }
    const unsigned F = 0xffffffffu;
#pragma unroll
    for (int off = 8; off <= 16; off <<= 1) {
        a0.x += __shfl_xor_sync(F, a0.x, off);
        a0.y += __shfl_xor_sync(F, a0.y, off);
        a0.z += __shfl_xor_sync(F, a0.z, off);
        a0.w += __shfl_xor_sync(F, a0.w, off);
        a1.x += __shfl_xor_sync(F, a1.x, off);
        a1.y += __shfl_xor_sync(F, a1.y, off);
        a1.z += __shfl_xor_sync(F, a1.z, off);
        a1.w += __shfl_xor_sync(F, a1.w, off);
    }
    // redistribute so lanes 0..15 write float4 index == lane (coalesced 256B)
    int tl = lane >> 1;
    float4 s0, s1;
    s0.x = __shfl_sync(F, a0.x, tl); s0.y = __shfl_sync(F, a0.y, tl);
    s0.z = __shfl_sync(F, a0.z, tl); s0.w = __shfl_sync(F, a0.w, tl);
    s1.x = __shfl_sync(F, a1.x, tl); s1.y = __shfl_sync(F, a1.y, tl);
    s1.z = __shfl_sync(F, a1.z, tl); s1.w = __shfl_sync(F, a1.w, tl);
    if (lane < 16) {
        float4* out4 = reinterpret_cast<float4*>(accOut);
        out4[(size_t)n * 16 + lane] = (lane & 1) ? s1 : s0;
    }
}

// ---------------------------------------------------------------------------
// Pool: per-graph sum of relu(dinv*acc3 + b3) with 4-node run-length batching.
__global__ void k_pool(const float* __restrict__ acc3, const float* __restrict__ b3,
                       const int* __restrict__ batch, int N) {
    int t = blockIdx.x * blockDim.x + threadIdx.x;
    int c = t & 63;
    int n0 = (t >> 6) * 4;
    if (n0 >= N) return;
    float b = b3[c];
    float accum = 0.f;
    int cnt = 0;
    int gprev = -1;
    for (int j = 0; j < 4; j++) {
        int n = n0 + j;
        if (n >= N) break;
        int g = batch[n];
        if ((unsigned)g >= NGRAPH) continue;
        if (g != gprev) {
            if (gprev >= 0) {
                atomicAdd(&g_gsum[gprev * NHID + c], accum);
                if (c == 0) atomicAdd(&g_gcnt[gprev], cnt);
            }
            accum = 0.f; cnt = 0; gprev = g;
        }
        accum += fmaxf(fmaf(g_dinv[n], acc3[(size_t)n * NHID + c], b), 0.f);
        cnt++;
    }
    if (gprev >= 0) {
        atomicAdd(&g_gsum[gprev * NHID + c], accum);
        if (c == 0) atomicAdd(&g_gcnt[gprev], cnt);
    }
}

__global__ void k_head(const float* __restrict__ Wl, const float* __restrict__ bl,
                       float* __restrict__ out) {
    int g = threadIdx.x;
    if (g >= NGRAPH) return;
    float cnt = fmaxf((float)g_gcnt[g], 1.f);
    float inv = 1.f / cnt;
    float l[NCLASS];
#pragma unroll
    for (int c = 0; c < NCLASS; c++) l[c] = bl[c];
    for (int k = 0; k < NHID; k++) {
        float p = g_gsum[g * NHID + k] * inv;
#pragma unroll
        for (int c = 0; c < NCLASS; c++) l[c] = fmaf(p, Wl[k * NCLASS + c], l[c]);
    }
    float m = l[0];
#pragma unroll
    for (int c = 1; c < NCLASS; c++) m = fmaxf(m, l[c]);
    float s = 0.f;
#pragma unroll
    for (int c = 0; c < NCLASS; c++) { l[c] = __expf(l[c] - m); s += l[c]; }
    float is = 1.f / s;
#pragma unroll
    for (int c = 0; c < NCLASS; c++) out[g * NCLASS + c] = l[c] * is;
}

// ---------------------------------------------------------------------------
extern "C" void kernel_launch(void* const* d_in, const int* in_sizes, int n_in,
                              void* d_out, int out_size) {
    const float* x     = (const float*)d_in[0];
    const int*   ei    = (const int*)d_in[1];
    const int*   batch = (const int*)d_in[2];
    const float* W1 = (const float*)d_in[3];
    const float* b1 = (const float*)d_in[4];
    const float* W2 = (const float*)d_in[5];
    const float* b2 = (const float*)d_in[6];
    const float* W3 = (const float*)d_in[7];
    const float* b3 = (const float*)d_in[8];
    const float* Wl = (const float*)d_in[9];
    const float* bl = (const float*)d_in[10];
    float* out = (float*)d_out;

    int N = in_sizes[0] / NFEAT;
    int E = in_sizes[1] / 2;

    float *accA = nullptr, *accB = nullptr;
    cudaGetSymbolAddress((void**)&accA, g_accA);
    cudaGetSymbolAddress((void**)&accB, g_accB);

    const int T = 256;
    int nScanBlocks = (N + SCAN_B - 1) / SCAN_B;

    k_init<<<(N + T - 1) / T, T>>>(N);
    k_edge_prep<<<(E + T - 1) / T, T>>>(ei, E, N);
    k_scanA<<<nScanBlocks, SCAN_B>>>(N);
    k_scanB<<<1, 256>>>(nScanBlocks);
    k_scanC<<<nScanBlocks, SCAN_B>>>(N);
    k_csr_fill<<<(E + T - 1) / T, T>>>(ei, E, N);

    int gemmBlocks = (N + 31) / 32;
    int aggBlocks = (N * 32 + T - 1) / T;

    // Layer 1
    k_gemm1<<<gemmBlocks, 128>>>(x, W1, N);
    k_agg<<<aggBlocks, T>>>(accA, N);
    // Layer 2
    k_gemm23<<<gemmBlocks, 128>>>(accA, b1, W2, N);
    k_agg<<<aggBlocks, T>>>(accB, N);
    // Layer 3
    k_gemm23<<<gemmBlocks, 128>>>(accB, b2, W3, N);
    k_agg<<<aggBlocks, T>>>(accA, N);

    // Pool + head
    k_pool<<<(((N + 3) / 4) * 64 + T - 1) / T, T>>>(accA, b3, batch, N);
    k_head<<<1, 64>>>(Wl, bl, out);
}

// round 8
// speedup vs baseline: 1.5121x; 1.2026x over previous
#include <cuda_runtime.h>
#include <cuda_fp16.h>

#define NMAX   100000
#define EMAX   1600000
#define NGRAPH 64
#define NFEAT  128
#define NHID   64
#define NCLASS 10
#define SCAN_B 512

// ---- scratch (allocation-free rule: __device__ globals) ----
__device__ int   g_csrc[EMAX];          // CSR: src ids grouped by dst
__device__ int   g_ecnt[NMAX];          // in-degree (edges only)
__device__ int   g_off[NMAX];           // CSR row offsets (exclusive scan)
__device__ int   g_cursor[NMAX];
__device__ int   g_scan[NMAX];
__device__ int   g_bsum[256];
__device__ int   g_boff[256];
__device__ float g_dinv[NMAX];
__device__ alignas(16) __half g_hs16[(size_t)NMAX * NHID];  // fp16 hs (gather src)
__device__ alignas(16) float  g_accA[(size_t)NMAX * NHID];
__device__ alignas(16) float  g_accB[(size_t)NMAX * NHID];
__device__ float g_gsum[NGRAPH * NHID];
__device__ int   g_gcnt[NGRAPH];

union H8I4 { int4 i; __half2 h[4]; };
union H4U2 { uint2 u; __half2 h[2]; };

// ---------------------------------------------------------------------------
__global__ void k_init(int N) {
    int i = blockIdx.x * blockDim.x + threadIdx.x;
    if (i < N) g_ecnt[i] = 0;
    if (i < NGRAPH * NHID) g_gsum[i] = 0.f;
    if (i < NGRAPH) g_gcnt[i] = 0;
}

// histogram in-degree straight from ei (no staging arrays)
__global__ void k_edge_prep(const int* __restrict__ ei, int E, int N) {
    int e = blockIdx.x * blockDim.x + threadIdx.x;
    if (e >= E) return;
    int s = ei[e];
    int d = ei[E + e];
    if ((unsigned)s >= (unsigned)N || (unsigned)d >= (unsigned)N) return;
    atomicAdd(&g_ecnt[d], 1);
}

// ---- 3-kernel exclusive scan of g_ecnt -> g_off -------------------------
__device__ __forceinline__ int block_incl_scan(int v, int tid) {
    __shared__ int wsum[16];
    int lane = tid & 31, w = tid >> 5;
    int x = v;
#pragma unroll
    for (int o = 1; o < 32; o <<= 1) {
        int t = __shfl_up_sync(0xffffffffu, x, o);
        if (lane >= o) x += t;
    }
    if (lane == 31) wsum[w] = x;
    __syncthreads();
    if (w == 0) {
        int y = (lane < (blockDim.x >> 5)) ? wsum[lane] : 0;
#pragma unroll
        for (int o = 1; o < 16; o <<= 1) {
            int t = __shfl_up_sync(0xffffffffu, y, o);
            if (lane >= o) y += t;
        }
        if (lane < 16) wsum[lane] = y;
    }
    __syncthreads();
    return x + (w > 0 ? wsum[w - 1] : 0);
}

__global__ void k_scanA(int N) {
    int i = blockIdx.x * SCAN_B + threadIdx.x;
    int v = (i < N) ? g_ecnt[i] : 0;
    int incl = block_incl_scan(v, threadIdx.x);
    if (i < N) g_scan[i] = incl - v;
    if (threadIdx.x == SCAN_B - 1) g_bsum[blockIdx.x] = incl;
}

__global__ void k_scanB(int nb) {
    int t = threadIdx.x;
    int v = (t < nb) ? g_bsum[t] : 0;
    int incl = block_incl_scan(v, t);
    if (t < 256) g_boff[t] = incl - v;
}

__global__ void k_scanC(int N) {
    int i = blockIdx.x * SCAN_B + threadIdx.x;
    if (i >= N) return;
    int off = g_scan[i] + g_boff[blockIdx.x];
    g_off[i] = off;
    g_cursor[i] = off;
    g_dinv[i] = rsqrtf((float)(g_ecnt[i] + 1));   // +1 self-loop
}

__global__ void k_csr_fill(const int* __restrict__ ei, int E, int N) {
    int e = blockIdx.x * blockDim.x + threadIdx.x;
    if (e >= E) return;
    int s = ei[e];
    int d = ei[E + e];
    if ((unsigned)s >= (unsigned)N || (unsigned)d >= (unsigned)N) return;
    int pos = atomicAdd(&g_cursor[d], 1);
    g_csrc[pos] = s;
}

// ---------------------------------------------------------------------------
// GEMM epilogue: scale 4 cols by dinv, convert to fp16, store 8B.
__device__ __forceinline__ void store_hs16(int n, int cg, float dv, float4 o) {
    H4U2 u;
    u.h[0] = __floats2half2_rn(o.x * dv, o.y * dv);
    u.h[1] = __floats2half2_rn(o.z * dv, o.w * dv);
    reinterpret_cast<uint2*>(g_hs16)[(size_t)n * 16 + cg] = u.u;
}

// Layer 1 GEMM: hs16[n] = fp16(dinv[n] * (x[n] @ W1)).
// 128 threads, 32 nodes/block; each thread: 4 nodes x 4 cols, k blocked by 4.
__global__ void k_gemm1(const float* __restrict__ x, const float* __restrict__ W, int N) {
    __shared__ float4 Wsh[NFEAT * 16];   // [k][c4]  32KB
    __shared__ float4 xsh[32 * 32];      // [node][k4] 16KB
    int tid = threadIdx.x;
    const float4* W4 = reinterpret_cast<const float4*>(W);
    const float4* x4 = reinterpret_cast<const float4*>(x);
#pragma unroll
    for (int i = tid; i < NFEAT * 16; i += 128) Wsh[i] = W4[i];
    int nb = blockIdx.x * 32;
#pragma unroll
    for (int i = tid; i < 32 * 32; i += 128) {
        int n = nb + (i >> 5);
        xsh[i] = (n < N) ? x4[(size_t)n * 32 + (i & 31)]
                         : make_float4(0.f, 0.f, 0.f, 0.f);
    }
    __syncthreads();

    int cg = tid & 15;        // col group: cols cg*4..cg*4+3
    int ng = tid >> 4;        // node group: nodes ng*4..ng*4+3
    float4 a[4];
#pragma unroll
    for (int j = 0; j < 4; j++) a[j] = make_float4(0.f, 0.f, 0.f, 0.f);

#pragma unroll 4
    for (int k4 = 0; k4 < 32; k4++) {
        float4 w0 = Wsh[(4 * k4 + 0) * 16 + cg];
        float4 w1 = Wsh[(4 * k4 + 1) * 16 + cg];
        float4 w2 = Wsh[(4 * k4 + 2) * 16 + cg];
        float4 w3 = Wsh[(4 * k4 + 3) * 16 + cg];
#pragma unroll
        for (int j = 0; j < 4; j++) {
            float4 xv = xsh[(ng * 4 + j) * 32 + k4];
            a[j].x = fmaf(xv.x, w0.x, a[j].x); a[j].y = fmaf(xv.x, w0.y, a[j].y);
            a[j].z = fmaf(xv.x, w0.z, a[j].z); a[j].w = fmaf(xv.x, w0.w, a[j].w);
            a[j].x = fmaf(xv.y, w1.x, a[j].x); a[j].y = fmaf(xv.y, w1.y, a[j].y);
            a[j].z = fmaf(xv.y, w1.z, a[j].z); a[j].w = fmaf(xv.y, w1.w, a[j].w);
            a[j].x = fmaf(xv.z, w2.x, a[j].x); a[j].y = fmaf(xv.z, w2.y, a[j].y);
            a[j].z = fmaf(xv.z, w2.z, a[j].z); a[j].w = fmaf(xv.z, w2.w, a[j].w);
            a[j].x = fmaf(xv.w, w3.x, a[j].x); a[j].y = fmaf(xv.w, w3.y, a[j].y);
            a[j].z = fmaf(xv.w, w3.z, a[j].z); a[j].w = fmaf(xv.w, w3.w, a[j].w);
        }
    }
#pragma unroll
    for (int j = 0; j < 4; j++) {
        int n = nb + ng * 4 + j;
        if (n < N) store_hs16(n, cg, g_dinv[n], a[j]);
    }
}

// Layers 2/3 GEMM: in = relu(dinv*accPrev + bPrev); hs16 = fp16(dinv*(in @ W)).
__global__ void k_gemm23(const float* __restrict__ accPrev, const float* __restrict__ bPrev,
                         const float* __restrict__ W, int N) {
    __shared__ float4 Wsh[NHID * 16];    // 16KB
    __shared__ float4 xsh[32 * 16];      // 8KB
    int tid = threadIdx.x;
    const float4* W4 = reinterpret_cast<const float4*>(W);
    const float4* acc4 = reinterpret_cast<const float4*>(accPrev);
    const float4* b4p = reinterpret_cast<const float4*>(bPrev);
#pragma unroll
    for (int i = tid; i < NHID * 16; i += 128) Wsh[i] = W4[i];
    int nb = blockIdx.x * 32;
#pragma unroll
    for (int i = tid; i < 32 * 16; i += 128) {
        int n = nb + (i >> 4);
        int k4 = i & 15;
        float4 o = make_float4(0.f, 0.f, 0.f, 0.f);
        if (n < N) {
            float4 av = acc4[(size_t)n * 16 + k4];
            float4 bb = b4p[k4];
            float dv = g_dinv[n];
            o.x = fmaxf(fmaf(dv, av.x, bb.x), 0.f);
            o.y = fmaxf(fmaf(dv, av.y, bb.y), 0.f);
            o.z = fmaxf(fmaf(dv, av.z, bb.z), 0.f);
            o.w = fmaxf(fmaf(dv, av.w, bb.w), 0.f);
        }
        xsh[i] = o;
    }
    __syncthreads();

    int cg = tid & 15;
    int ng = tid >> 4;
    float4 a[4];
#pragma unroll
    for (int j = 0; j < 4; j++) a[j] = make_float4(0.f, 0.f, 0.f, 0.f);

#pragma unroll 4
    for (int k4 = 0; k4 < 16; k4++) {
        float4 w0 = Wsh[(4 * k4 + 0) * 16 + cg];
        float4 w1 = Wsh[(4 * k4 + 1) * 16 + cg];
        float4 w2 = Wsh[(4 * k4 + 2) * 16 + cg];
        float4 w3 = Wsh[(4 * k4 + 3) * 16 + cg];
#pragma unroll
        for (int j = 0; j < 4; j++) {
            float4 xv = xsh[(ng * 4 + j) * 16 + k4];
            a[j].x = fmaf(xv.x, w0.x, a[j].x); a[j].y = fmaf(xv.x, w0.y, a[j].y);
            a[j].z = fmaf(xv.x, w0.z, a[j].z); a[j].w = fmaf(xv.x, w0.w, a[j].w);
            a[j].x = fmaf(xv.y, w1.x, a[j].x); a[j].y = fmaf(xv.y, w1.y, a[j].y);
            a[j].z = fmaf(xv.y, w1.z, a[j].z); a[j].w = fmaf(xv.y, w1.w, a[j].w);
            a[j].x = fmaf(xv.z, w2.x, a[j].x); a[j].y = fmaf(xv.z, w2.y, a[j].y);
            a[j].z = fmaf(xv.z, w2.z, a[j].z); a[j].w = fmaf(xv.z, w2.w, a[j].w);
            a[j].x = fmaf(xv.w, w3.x, a[j].x); a[j].y = fmaf(xv.w, w3.y, a[j].y);
            a[j].z = fmaf(xv.w, w3.z, a[j].z); a[j].w = fmaf(xv.w, w3.w, a[j].w);
        }
    }
#pragma unroll
    for (int j = 0; j < 4; j++) {
        int n = nb + ng * 4 + j;
        if (n < N) store_hs16(n, cg, g_dinv[n], a[j]);
    }
}

// ---------------------------------------------------------------------------
// CSR gather aggregation (fp16 source, HADD2 slot accumulate, fp32 reduce):
// acc[n] = hs[n] (self-loop) + sum_{s in in(n)} hs[s].
// One warp per node; 8 lanes x 16B (8 halves) cover the 128B row; 4 edge slots.
__global__ void k_agg(float* __restrict__ accOut, int N) {
    int warp = (blockIdx.x * blockDim.x + threadIdx.x) >> 5;
    if (warp >= N) return;
    int lane = threadIdx.x & 31;
    int p = lane & 7;        // 16B chunk (cols p*8 .. p*8+7)
    int q = lane >> 3;       // edge slot 0..3
    const int4* h16 = reinterpret_cast<const int4*>(g_hs16);
    const int* __restrict__ csrc = g_csrc;
    int n = warp;
    int start = g_off[n];
    int end = start + g_ecnt[n];

    __half2 a[4];
    if (q == 0) {            // self-loop init
        H8I4 v; v.i = h16[(size_t)n * 8 + p];
#pragma unroll
        for (int i = 0; i < 4; i++) a[i] = v.h[i];
    } else {
#pragma unroll
        for (int i = 0; i < 4; i++) a[i] = __half2half2(__ushort_as_half(0));
    }
    int j = start + q;
    for (; j + 4 < end; j += 8) {
        int sA = csrc[j];
        int sB = csrc[j + 4];
        H8I4 vA; vA.i = h16[(size_t)sA * 8 + p];
        H8I4 vB; vB.i = h16[(size_t)sB * 8 + p];
#pragma unroll
        for (int i = 0; i < 4; i++) a[i] = __hadd2(a[i], vA.h[i]);
#pragma unroll
        for (int i = 0; i < 4; i++) a[i] = __hadd2(a[i], vB.h[i]);
    }
    if (j < end) {
        int s = csrc[j];
        H8I4 v; v.i = h16[(size_t)s * 8 + p];
#pragma unroll
        for (int i = 0; i < 4; i++) a[i] = __hadd2(a[i], v.h[i]);
    }
    // convert to fp32, reduce across the 4 edge slots in fp32
    float f[8];
#pragma unroll
    for (int i = 0; i < 4; i++) {
        float2 t = __half22float2(a[i]);
        f[2 * i] = t.x; f[2 * i + 1] = t.y;
    }
    const unsigned F = 0xffffffffu;
#pragma unroll
    for (int off = 8; off <= 16; off <<= 1) {
#pragma unroll
        for (int i = 0; i < 8; i++) f[i] += __shfl_xor_sync(F, f[i], off);
    }
    if (lane < 8) {
        float4* out4 = reinterpret_cast<float4*>(accOut);
        out4[(size_t)n * 16 + lane * 2]     = make_float4(f[0], f[1], f[2], f[3]);
        out4[(size_t)n * 16 + lane * 2 + 1] = make_float4(f[4], f[5], f[6], f[7]);
    }
}

// ---------------------------------------------------------------------------
// Pool: per-graph sum of relu(dinv*acc3 + b3) with 4-node run-length batching.
__global__ void k_pool(const float* __restrict__ acc3, const float* __restrict__ b3,
                       const int* __restrict__ batch, int N) {
    int t = blockIdx.x * blockDim.x + threadIdx.x;
    int c = t & 63;
    int n0 = (t >> 6) * 4;
    if (n0 >= N) return;
    float b = b3[c];
    float accum = 0.f;
    int cnt = 0;
    int gprev = -1;
    for (int j = 0; j < 4; j++) {
        int n = n0 + j;
        if (n >= N) break;
        int g = batch[n];
        if ((unsigned)g >= NGRAPH) continue;
        if (g != gprev) {
            if (gprev >= 0) {
                atomicAdd(&g_gsum[gprev * NHID + c], accum);
                if (c == 0) atomicAdd(&g_gcnt[gprev], cnt);
            }
            accum = 0.f; cnt = 0; gprev = g;
        }
        accum += fmaxf(fmaf(g_dinv[n], acc3[(size_t)n * NHID + c], b), 0.f);
        cnt++;
    }
    if (gprev >= 0) {
        atomicAdd(&g_gsum[gprev * NHID + c], accum);
        if (c == 0) atomicAdd(&g_gcnt[gprev], cnt);
    }
}

__global__ void k_head(const float* __restrict__ Wl, const float* __restrict__ bl,
                       float* __restrict__ out) {
    int g = threadIdx.x;
    if (g >= NGRAPH) return;
    float cnt = fmaxf((float)g_gcnt[g], 1.f);
    float inv = 1.f / cnt;
    float l[NCLASS];
#pragma unroll
    for (int c = 0; c < NCLASS; c++) l[c] = bl[c];
    for (int k = 0; k < NHID; k++) {
        float p = g_gsum[g * NHID + k] * inv;
#pragma unroll
        for (int c = 0; c < NCLASS; c++) l[c] = fmaf(p, Wl[k * NCLASS + c], l[c]);
    }
    float m = l[0];
#pragma unroll
    for (int c = 1; c < NCLASS; c++) m = fmaxf(m, l[c]);
    float s = 0.f;
#pragma unroll
    for (int c = 0; c < NCLASS; c++) { l[c] = __expf(l[c] - m); s += l[c]; }
    float is = 1.f / s;
#pragma unroll
    for (int c = 0; c < NCLASS; c++) out[g * NCLASS + c] = l[c] * is;
}

// ---------------------------------------------------------------------------
extern "C" void kernel_launch(void* const* d_in, const int* in_sizes, int n_in,
                              void* d_out, int out_size) {
    const float* x     = (const float*)d_in[0];
    const int*   ei    = (const int*)d_in[1];
    const int*   batch = (const int*)d_in[2];
    const float* W1 = (const float*)d_in[3];
    const float* b1 = (const float*)d_in[4];
    const float* W2 = (const float*)d_in[5];
    const float* b2 = (const float*)d_in[6];
    const float* W3 = (const float*)d_in[7];
    const float* b3 = (const float*)d_in[8];
    const float* Wl = (const float*)d_in[9];
    const float* bl = (const float*)d_in[10];
    float* out = (float*)d_out;

    int N = in_sizes[0] / NFEAT;
    int E = in_sizes[1] / 2;

    float *accA = nullptr, *accB = nullptr;
    cudaGetSymbolAddress((void**)&accA, g_accA);
    cudaGetSymbolAddress((void**)&accB, g_accB);

    const int T = 256;
    int nScanBlocks = (N + SCAN_B - 1) / SCAN_B;

    k_init<<<(N + T - 1) / T, T>>>(N);
    k_edge_prep<<<(E + T - 1) / T, T>>>(ei, E, N);
    k_scanA<<<nScanBlocks, SCAN_B>>>(N);
    k_scanB<<<1, 256>>>(nScanBlocks);
    k_scanC<<<nScanBlocks, SCAN_B>>>(N);
    k_csr_fill<<<(E + T - 1) / T, T>>>(ei, E, N);

    int gemmBlocks = (N + 31) / 32;
    int aggBlocks = (N * 32 + T - 1) / T;

    // Layer 1
    k_gemm1<<<gemmBlocks, 128>>>(x, W1, N);
    k_agg<<<aggBlocks, T>>>(accA, N);
    // Layer 2
    k_gemm23<<<gemmBlocks, 128>>>(accA, b1, W2, N);
    k_agg<<<aggBlocks, T>>>(accB, N);
    // Layer 3
    k_gemm23<<<gemmBlocks, 128>>>(accB, b2, W3, N);
    k_agg<<<aggBlocks, T>>>(accA, N);

    // Pool + head
    k_pool<<<(((N + 3) / 4) * 64 + T - 1) / T, T>>>(accA, b3, batch, N);
    k_head<<<1, 64>>>(Wl, bl, out);
}